// round 15
// baseline (speedup 1.0000x reference)
#include <cuda_runtime.h>

// Problem constants
static constexpr int Tt = 4;
static constexpr int Bb = 16;
static constexpr int Cc = 512;
static constexpr int Nn = 1024;
static constexpr int Cr = 64;
static constexpr int TB = Tt * Bb;       // 64 rows
static constexpr int BC = Bb * Cc;       // 8192 channels
static constexpr int NBLK_A = BC / 2;    // 4096 phase-A blocks (2 channels each)
static constexpr int NTAIL  = Cc;        // 512 tail blocks (one phase-C column each)

// Scratch (allocation-free: __device__ globals)
__device__ float g_buf[TB * Cc];         // GAP output [64, 512] row-major [r][c]
__device__ float h1n_buf[TB * Cr];       // bn1 output ROW-major [r][j]
// Monotonic counters (never reset; each launch adds exactly NBLK_A / Cr /
// NTAIL respectively, so ceil-division epoch ids are launch-count
// independent — mechanism proven R3..R14).
__device__ unsigned g_done;              // phase-A completions
__device__ unsigned g_bdone;             // phase-B completions (64/launch)
__device__ unsigned g_tail;              // tail-block arrivals (512/launch)

// Scaled-LIF step (exact, bit-identical; verified rel_err=0 R9..R14):
// u_t = v_t * 2^t; u += x*2^t; spike iff u >= 2^(t+1); hard reset u = 0.
#define ULIF(u, xv, CT, TH, pk, INC) \
    do { u = fmaf((xv), (CT), u); if (u >= (TH)) { pk += (INC); u = 0.0f; } } while (0)

__global__ void __launch_bounds__(256)
snn_kernel(const float* __restrict__ x,
           const float* __restrict__ w1, const float* __restrict__ b1,
           const float* __restrict__ gamma1, const float* __restrict__ beta1,
           const float* __restrict__ w2, const float* __restrict__ b2,
           const float* __restrict__ gamma2, const float* __restrict__ beta2,
           float* __restrict__ out)
{
    const int tid  = threadIdx.x;
    const int lane = tid & 31;
    const int warp = tid >> 5;

    __shared__ unsigned sdata[8][2];   // phase A packed counts [warp][ch]
    __shared__ unsigned sepoch;        // tail: launch epoch broadcast
    __shared__ float ws[Cc];           // phase B: w1 row
    __shared__ float h1s[TB];          // phase B: column values
    __shared__ float stats[2];         // phase B: mu, scale
    __shared__ float w2s[Cr];          // phase C: w2 row
    __shared__ float wsum[4];          // phase C: warp partials

    // =====================================================================
    // Phase A blocks: one-shot LIF + GAP (flat R2/R8-proven shape).
    // =====================================================================
    if (blockIdx.x < NBLK_A) {
        const int bc0 = blockIdx.x * 2;
        const int bc1 = bc0 + 1;
        const float4* __restrict__ xp = reinterpret_cast<const float4*>(x);

        float4 xa[Tt], xb[Tt];
        #pragma unroll
        for (int t = 0; t < Tt; t++) {
            xa[t] = xp[(size_t)(t * BC + bc0) * 256 + tid];
            xb[t] = xp[(size_t)(t * BC + bc1) * 256 + tid];
        }

        float ua0=0.f, ua1=0.f, ua2=0.f, ua3=0.f;
        float ub0=0.f, ub1=0.f, ub2=0.f, ub3=0.f;
        unsigned pa = 0u, pb = 0u;

        #pragma unroll
        for (int t = 0; t < Tt; t++) {
            const float    CT  = (float)(1 << t);   // 2^t
            const float    TH  = (float)(2 << t);   // 2^(t+1)
            const unsigned INC = 1u << (8 * t);
            ULIF(ua0, xa[t].x, CT, TH, pa, INC);
            ULIF(ua1, xa[t].y, CT, TH, pa, INC);
            ULIF(ua2, xa[t].z, CT, TH, pa, INC);
            ULIF(ua3, xa[t].w, CT, TH, pa, INC);
            ULIF(ub0, xb[t].x, CT, TH, pb, INC);
            ULIF(ub1, xb[t].y, CT, TH, pb, INC);
            ULIF(ub2, xb[t].z, CT, TH, pb, INC);
            ULIF(ub3, xb[t].w, CT, TH, pb, INC);
        }

        pa = __reduce_add_sync(0xffffffffu, pa);
        pb = __reduce_add_sync(0xffffffffu, pb);
        if (lane == 0) { sdata[warp][0] = pa; sdata[warp][1] = pb; }
        __syncthreads();

        if (tid < 8) {
            const int ch = tid >> 2;
            const int t  = tid & 3;
            unsigned s = 0;
            #pragma unroll
            for (int w = 0; w < 8; w++)
                s += (sdata[w][ch] >> (8 * t)) & 0xFFu;
            // g[r][c] row-major: (t*Bb + b)*Cc + c == t*BC + bc
            g_buf[t * BC + bc0 + ch] = (float)s * (1.0f / (float)Nn);
        }
        __syncthreads();
        if (tid == 0) {
            __threadfence();                 // publish g_buf
            atomicAdd(&g_done, 1u);
        }
        return;
    }

    // =====================================================================
    // Tail blocks (512, placed last in bid order). j = output column.
    // =====================================================================
    const int j = blockIdx.x - NBLK_A;     // 0..511

    // Launch epoch from own arrival counter (512 arrivals/launch).
    if (tid == 0) {
        unsigned v = atomicAdd(&g_tail, 1u) + 1u;
        sepoch = (v + (unsigned)NTAIL - 1u) / (unsigned)NTAIL;
    }
    __syncthreads();
    const unsigned epoch = sepoch;

    // Prefetch weights into smem BEFORE spinning (latency hidden by spin).
    if (j < Cr) {
        ws[tid]       = w1[(size_t)j * Cc + tid];
        ws[tid + 256] = w1[(size_t)j * Cc + tid + 256];
    }
    if (tid < Cr) w2s[tid] = w2[(size_t)j * Cr + tid];

    // ---- Phase B (blocks j < 64 only): mm1 + bn1 for column j ----
    if (j < Cr) {
        if (tid == 0) {
            while (*(volatile unsigned*)&g_done < epoch * (unsigned)NBLK_A)
                __nanosleep(64);
            __threadfence();
        }
        __syncthreads();

        float acc[8];
        #pragma unroll
        for (int k = 0; k < 8; k++) acc[k] = 0.f;

        #pragma unroll
        for (int i = 0; i < 16; i++) {
            const int col = i * 32 + lane;
            const float wv = ws[col];
            #pragma unroll
            for (int k = 0; k < 8; k++)
                acc[k] += g_buf[(size_t)(warp * 8 + k) * Cc + col] * wv;
        }

        const float b1j = b1[j];
        #pragma unroll
        for (int k = 0; k < 8; k++) {
            float v = acc[k];
            #pragma unroll
            for (int off = 16; off > 0; off >>= 1)
                v += __shfl_down_sync(0xffffffffu, v, off);
            if (lane == 0) h1s[warp * 8 + k] = v + b1j;
        }
        __syncthreads();

        if (warp == 0) {
            float a = h1s[lane], b = h1s[lane + 32];
            float s  = a + b;
            float ss = a * a + b * b;
            #pragma unroll
            for (int off = 16; off > 0; off >>= 1) {
                s  += __shfl_down_sync(0xffffffffu, s,  off);
                ss += __shfl_down_sync(0xffffffffu, ss, off);
            }
            if (lane == 0) {
                float mu  = s * (1.0f / TB);
                float var = ss * (1.0f / TB) - mu * mu;
                if (var < 0.f) var = 0.f;
                stats[0] = mu;
                stats[1] = rsqrtf(var + 1e-5f) * gamma1[j];
            }
        }
        __syncthreads();

        // ROW-major store: h1n[r][j]
        if (tid < TB)
            h1n_buf[tid * Cr + j] = (h1s[tid] - stats[0]) * stats[1] + beta1[j];

        __syncthreads();
        if (tid == 0) {
            __threadfence();                 // publish h1n column
            atomicAdd(&g_bdone, 1u);
        }
    }

    // ---- wait for ALL 64 phase-B columns ----
    if (tid == 0) {
        while (*(volatile unsigned*)&g_bdone < epoch * (unsigned)Cr)
            __nanosleep(32);
        __threadfence();
    }
    __syncthreads();

    // ---- Phase C: mm2 + bn2 + out for column j; thread r < 64 owns row r.
    //      h1n row r read directly from L2 as 16 float4s (no smem staging).
    {
        float h = 0.f;
        if (tid < TB) {
            const int r = tid;
            const float4* __restrict__ hp =
                reinterpret_cast<const float4*>(h1n_buf + (size_t)r * Cr);
            float acc = 0.f;
            #pragma unroll
            for (int k = 0; k < 16; k++) {
                const float4 v = hp[k];
                acc += v.x * w2s[4 * k + 0];
                acc += v.y * w2s[4 * k + 1];
                acc += v.z * w2s[4 * k + 2];
                acc += v.w * w2s[4 * k + 3];
            }
            h = acc + b2[j];

            float s = h, ss = h * h;
            #pragma unroll
            for (int off = 16; off > 0; off >>= 1) {
                s  += __shfl_down_sync(0xffffffffu, s,  off);
                ss += __shfl_down_sync(0xffffffffu, ss, off);
            }
            if (lane == 0) { wsum[warp * 2] = s; wsum[warp * 2 + 1] = ss; }
        }
        __syncthreads();

        if (tid < TB) {
            const float S  = wsum[0] + wsum[2];
            const float SS = wsum[1] + wsum[3];
            const float mu = S * (1.0f / TB);
            float var = SS * (1.0f / TB) - mu * mu;
            if (var < 0.f) var = 0.f;
            const float sc = rsqrtf(var + 1e-5f) * gamma2[j];
            out[tid * Cc + j] = (h - mu) * sc + beta2[j];
        }
    }
}

// ---------------------------------------------------------------------------
extern "C" void kernel_launch(void* const* d_in, const int* in_sizes, int n_in,
                              void* d_out, int out_size) {
    const float* x      = (const float*)d_in[0];
    const float* w1     = (const float*)d_in[1];
    const float* b1     = (const float*)d_in[2];
    const float* gamma1 = (const float*)d_in[3];
    const float* beta1  = (const float*)d_in[4];
    const float* w2     = (const float*)d_in[5];
    const float* b2     = (const float*)d_in[6];
    const float* gamma2 = (const float*)d_in[7];
    const float* beta2  = (const float*)d_in[8];
    float* out = (float*)d_out;

    snn_kernel<<<NBLK_A + NTAIL, 256>>>(x, w1, b1, gamma1, beta1,
                                        w2, b2, gamma2, beta2, out);
}